// round 4
// baseline (speedup 1.0000x reference)
#include <cuda_runtime.h>
#include <math.h>

// Problem shape (fixed by dataset)
static constexpr int Bb = 4;
static constexpr int Ss = 2048;
static constexpr int Ee = 1024;
static constexpr int Dd = 1024;

// Scratch (allocation-free: __device__ globals). P is PER-BATCH (16 MB) and
// reused across the 4 batches via stream-ordered kernel launches.
__device__ float g_q[(size_t)Bb * Ss * Dd];   // 32 MB
__device__ float g_k[(size_t)Bb * Ss * Dd];   // 32 MB
__device__ float g_v[(size_t)Bb * Ss * Dd];   // 32 MB
__device__ float g_p[(size_t)Ss * Ss];        // 16 MB (one batch)

#define BM 128
#define BN 128
#define BK 16
#define TM 8
#define TN 8
// 256 threads = 16x16 grid of 8x8 microtiles

// C[m,n] = sum_k A[m,k] * W[n,k]  (row-major, K contiguous; "NT").
// which: 0->g_q, 1->g_k, 2->g_v output.
__global__ void __launch_bounds__(256) proj_nt(
    const float* __restrict__ A, const float* __restrict__ W, int which)
{
    float* C = (which == 0) ? g_q : (which == 1) ? g_k : g_v;
    const int K = Ee, N = Dd;
    int bx = blockIdx.x, by = blockIdx.y;

    __shared__ float As[BK][BM];
    __shared__ float Bs[BK][BN];

    int tid = threadIdx.x;
    int tr = (tid >> 4) * TM;
    int tc = (tid & 15) * TN;

    float acc[TM][TN] = {};
    float ra[TM], rb[TN];

    const float* Ab = A + (size_t)(by * BM) * K;
    const float* Bt = W + (size_t)(bx * BN) * K;

    for (int k0 = 0; k0 < K; k0 += BK) {
        #pragma unroll
        for (int j = 0; j < 2; j++) {
            int i = tid + j * 256, row = i >> 2, c4 = (i & 3) * 4;
            float4 t = *(const float4*)(Ab + (size_t)row * K + k0 + c4);
            As[c4 + 0][row] = t.x; As[c4 + 1][row] = t.y;
            As[c4 + 2][row] = t.z; As[c4 + 3][row] = t.w;
        }
        #pragma unroll
        for (int j = 0; j < 2; j++) {
            int i = tid + j * 256, row = i >> 2, c4 = (i & 3) * 4;
            float4 t = *(const float4*)(Bt + (size_t)row * K + k0 + c4);
            Bs[c4 + 0][row] = t.x; Bs[c4 + 1][row] = t.y;
            Bs[c4 + 2][row] = t.z; Bs[c4 + 3][row] = t.w;
        }
        __syncthreads();
        #pragma unroll
        for (int kk = 0; kk < BK; kk++) {
            #pragma unroll
            for (int i = 0; i < TM; i++) ra[i] = As[kk][tr + i];
            #pragma unroll
            for (int j = 0; j < TN; j++) rb[j] = Bs[kk][tc + j];
            #pragma unroll
            for (int i = 0; i < TM; i++)
                #pragma unroll
                for (int j = 0; j < TN; j++)
                    acc[i][j] += ra[i] * rb[j];
        }
        __syncthreads();
    }

    #pragma unroll
    for (int i = 0; i < TM; i++) {
        float* crow = C + (size_t)(by * BM + tr + i) * N + bx * BN + tc;
        *(float4*)(crow)     = make_float4(acc[i][0], acc[i][1], acc[i][2], acc[i][3]);
        *(float4*)(crow + 4) = make_float4(acc[i][4], acc[i][5], acc[i][6], acc[i][7]);
    }
}

// P[s,t] = sum_d q[b,s,d] * k[b,t,d] for one batch b; skip tiles above diagonal.
__global__ void __launch_bounds__(256) scores_nt(int b)
{
    int bx = blockIdx.x, by = blockIdx.y;
    if (BN * bx > BM * by + (BM - 1)) return;  // entirely masked tile

    const int K = Dd, N = Ss;
    const float* A  = g_q + (size_t)b * Ss * Dd;
    const float* Bt = g_k + (size_t)b * Ss * Dd;
    float*       C  = g_p;

    __shared__ float As[BK][BM];
    __shared__ float Bs[BK][BN];

    int tid = threadIdx.x;
    int tr = (tid >> 4) * TM;
    int tc = (tid & 15) * TN;

    float acc[TM][TN] = {};
    float ra[TM], rb[TN];

    const float* Ab  = A  + (size_t)(by * BM) * K;
    const float* Bb2 = Bt + (size_t)(bx * BN) * K;

    for (int k0 = 0; k0 < K; k0 += BK) {
        #pragma unroll
        for (int j = 0; j < 2; j++) {
            int i = tid + j * 256, row = i >> 2, c4 = (i & 3) * 4;
            float4 t = *(const float4*)(Ab + (size_t)row * K + k0 + c4);
            As[c4 + 0][row] = t.x; As[c4 + 1][row] = t.y;
            As[c4 + 2][row] = t.z; As[c4 + 3][row] = t.w;
        }
        #pragma unroll
        for (int j = 0; j < 2; j++) {
            int i = tid + j * 256, row = i >> 2, c4 = (i & 3) * 4;
            float4 t = *(const float4*)(Bb2 + (size_t)row * K + k0 + c4);
            Bs[c4 + 0][row] = t.x; Bs[c4 + 1][row] = t.y;
            Bs[c4 + 2][row] = t.z; Bs[c4 + 3][row] = t.w;
        }
        __syncthreads();
        #pragma unroll
        for (int kk = 0; kk < BK; kk++) {
            #pragma unroll
            for (int i = 0; i < TM; i++) ra[i] = As[kk][tr + i];
            #pragma unroll
            for (int j = 0; j < TN; j++) rb[j] = Bs[kk][tc + j];
            #pragma unroll
            for (int i = 0; i < TM; i++)
                #pragma unroll
                for (int j = 0; j < TN; j++)
                    acc[i][j] += ra[i] * rb[j];
        }
        __syncthreads();
    }

    #pragma unroll
    for (int i = 0; i < TM; i++) {
        float* crow = C + (size_t)(by * BM + tr + i) * N + bx * BN + tc;
        *(float4*)(crow)     = make_float4(acc[i][0], acc[i][1], acc[i][2], acc[i][3]);
        *(float4*)(crow + 4) = make_float4(acc[i][4], acc[i][5], acc[i][6], acc[i][7]);
    }
}

// Row-wise causal softmax on g_p (one batch, in place). Applies 1/sqrt(D)
// inside like the reference; zeroes masked tail so AV is dense in-band.
__global__ void __launch_bounds__(256) softmax_causal()
{
    const int S = Ss;
    int s = blockIdx.x;
    float* p = g_p + (size_t)s * S;
    int L = s + 1;
    const float scale = 0.03125f;  // 1/sqrt(1024)
    int tid = threadIdx.x;

    __shared__ float red[8];

    float m = -1e30f;
    for (int i = tid; i < L; i += 256) m = fmaxf(m, p[i]);
    #pragma unroll
    for (int o = 16; o; o >>= 1) m = fmaxf(m, __shfl_xor_sync(0xFFFFFFFFu, m, o));
    if ((tid & 31) == 0) red[tid >> 5] = m;
    __syncthreads();
    if (tid == 0) {
        float mm = red[0];
        #pragma unroll
        for (int i = 1; i < 8; i++) mm = fmaxf(mm, red[i]);
        red[0] = mm;
    }
    __syncthreads();
    m = red[0] * scale;
    __syncthreads();

    float sum = 0.f;
    for (int i = tid; i < L; i += 256) sum += __expf(p[i] * scale - m);
    #pragma unroll
    for (int o = 16; o; o >>= 1) sum += __shfl_xor_sync(0xFFFFFFFFu, sum, o);
    if ((tid & 31) == 0) red[tid >> 5] = sum;
    __syncthreads();
    if (tid == 0) {
        float ss = 0.f;
        #pragma unroll
        for (int i = 0; i < 8; i++) ss += red[i];
        red[0] = ss;
    }
    __syncthreads();
    float inv = 1.0f / red[0];

    for (int i = tid; i < S; i += 256)
        p[i] = (i < L) ? __expf(p[i] * scale - m) * inv : 0.0f;
}

// out[b,s,d] = sum_t P[s,t] * V[b,t,d]  ("NN"), k-loop stops at diagonal.
__global__ void __launch_bounds__(256) av_nn(float* __restrict__ out, int b)
{
    int bx = blockIdx.x, by = blockIdx.y;
    const int K = Ss, N = Dd;
    const float* A  = g_p;
    const float* Bm = g_v + (size_t)b * Ss * Dd;
    float*       C  = out + (size_t)b * Ss * Dd;

    int kmax = (by + 1) * BM;
    if (kmax > K) kmax = K;

    __shared__ float As[BK][BM];
    __shared__ float Bs[BK][BN];

    int tid = threadIdx.x;
    int tr = (tid >> 4) * TM;
    int tc = (tid & 15) * TN;

    float acc[TM][TN] = {};
    float ra[TM], rb[TN];

    const float* Ab = A + (size_t)(by * BM) * K;

    for (int k0 = 0; k0 < kmax; k0 += BK) {
        #pragma unroll
        for (int j = 0; j < 2; j++) {
            int i = tid + j * 256, row = i >> 2, c4 = (i & 3) * 4;
            float4 t = *(const float4*)(Ab + (size_t)row * K + k0 + c4);
            As[c4 + 0][row] = t.x; As[c4 + 1][row] = t.y;
            As[c4 + 2][row] = t.z; As[c4 + 3][row] = t.w;
        }
        #pragma unroll
        for (int j = 0; j < 2; j++) {
            int i = tid + j * 256, row = i >> 5, cc = (i & 31) * 4;
            float4 t = *(const float4*)(Bm + (size_t)(k0 + row) * N + bx * BN + cc);
            *(float4*)&Bs[row][cc] = t;
        }
        __syncthreads();
        #pragma unroll
        for (int kk = 0; kk < BK; kk++) {
            #pragma unroll
            for (int i = 0; i < TM; i++) ra[i] = As[kk][tr + i];
            #pragma unroll
            for (int j = 0; j < TN; j++) rb[j] = Bs[kk][tc + j];
            #pragma unroll
            for (int i = 0; i < TM; i++)
                #pragma unroll
                for (int j = 0; j < TN; j++)
                    acc[i][j] += ra[i] * rb[j];
        }
        __syncthreads();
    }

    #pragma unroll
    for (int i = 0; i < TM; i++) {
        float* crow = C + (size_t)(by * BM + tr + i) * N + bx * BN + tc;
        *(float4*)(crow)     = make_float4(acc[i][0], acc[i][1], acc[i][2], acc[i][3]);
        *(float4*)(crow + 4) = make_float4(acc[i][4], acc[i][5], acc[i][6], acc[i][7]);
    }
}

extern "C" void kernel_launch(void* const* d_in, const int* in_sizes, int n_in,
                              void* d_out, int out_size)
{
    const float* x  = (const float*)d_in[0];
    const float* wq = (const float*)d_in[1];
    const float* wk = (const float*)d_in[2];
    const float* wv = (const float*)d_in[3];
    float* out = (float*)d_out;

    dim3 blk(256);

    dim3 gproj(Dd / BN, (Bb * Ss) / BM, 1);
    proj_nt<<<gproj, blk>>>(x, wq, 0);
    proj_nt<<<gproj, blk>>>(x, wk, 1);
    proj_nt<<<gproj, blk>>>(x, wv, 2);

    dim3 gsc(Ss / BN, Ss / BM, 1);
    dim3 gav(Dd / BN, Ss / BM, 1);
    for (int b = 0; b < Bb; b++) {
        // stream order serializes: scores -> softmax -> av reuse g_p safely
        scores_nt<<<gsc, blk>>>(b);
        softmax_causal<<<Ss, blk>>>();
        av_nn<<<gav, blk>>>(out, b);
    }
}

// round 5
// speedup vs baseline: 1.5888x; 1.5888x over previous
#include <cuda_runtime.h>
#include <math.h>

// Problem shape (fixed by dataset)
static constexpr int Bb = 4;
static constexpr int Ss = 2048;
static constexpr int Ee = 1024;
static constexpr int Dd = 1024;

// Scratch (allocation-free: __device__ globals)
__device__ float g_q[(size_t)Bb * Ss * Dd];   // 32 MB
__device__ float g_k[(size_t)Bb * Ss * Dd];   // 32 MB
__device__ float g_v[(size_t)Bb * Ss * Dd];   // 32 MB
__device__ float g_p[(size_t)Bb * Ss * Ss];   // 67 MB (full, all batches)

#define BM 128
#define BN 128
#define BK 16
#define TM 8
#define TN 8
// 256 threads = 16x16 grid of 8x8 microtiles; double-buffered smem.

// ---- shared compute macro: 16-deep rank-1 updates on buffer `buf` ----
#define COMPUTE_TILE(buf)                                                     \
    _Pragma("unroll")                                                         \
    for (int kk = 0; kk < BK; kk++) {                                         \
        float4 a0 = *(const float4*)&As[buf][kk][tr];                         \
        float4 a1 = *(const float4*)&As[buf][kk][tr + 4];                     \
        float4 b0 = *(const float4*)&Bs[buf][kk][tc];                         \
        float4 b1 = *(const float4*)&Bs[buf][kk][tc + 4];                     \
        float ra[8] = {a0.x, a0.y, a0.z, a0.w, a1.x, a1.y, a1.z, a1.w};       \
        float rb[8] = {b0.x, b0.y, b0.z, b0.w, b1.x, b1.y, b1.z, b1.w};       \
        _Pragma("unroll")                                                     \
        for (int i = 0; i < TM; i++)                                          \
            _Pragma("unroll")                                                 \
            for (int j = 0; j < TN; j++)                                      \
                acc[i][j] += ra[i] * rb[j];                                   \
    }

#define STORE_KT(dst, b_, v0, v1)                                             \
    dst[b_][lc4 + 0][lrow]      = v0.x;                                       \
    dst[b_][lc4 + 1][lrow]      = v0.y;                                       \
    dst[b_][lc4 + 2][lrow]      = v0.z;                                       \
    dst[b_][lc4 + 3][lrow]      = v0.w;                                       \
    dst[b_][lc4 + 0][lrow + 64] = v1.x;                                       \
    dst[b_][lc4 + 1][lrow + 64] = v1.y;                                       \
    dst[b_][lc4 + 2][lrow + 64] = v1.z;                                       \
    dst[b_][lc4 + 3][lrow + 64] = v1.w;

#define EPILOGUE(Cp, N_)                                                      \
    _Pragma("unroll")                                                         \
    for (int i = 0; i < TM; i++) {                                            \
        float* crow = Cp + (size_t)(by * BM + tr + i) * N_ + bx * BN + tc;    \
        *(float4*)(crow)     = make_float4(acc[i][0], acc[i][1], acc[i][2], acc[i][3]); \
        *(float4*)(crow + 4) = make_float4(acc[i][4], acc[i][5], acc[i][6], acc[i][7]); \
    }

// ---------------------------------------------------------------------------
// Fused QKV projection: z selects W/output. NT GEMM, M=8192, N=K=1024.
__global__ void __launch_bounds__(256, 2) proj_all(
    const float* __restrict__ x,
    const float* __restrict__ wq, const float* __restrict__ wk,
    const float* __restrict__ wv)
{
    const int K = Ee, N = Dd;
    int bx = blockIdx.x, by = blockIdx.y, bz = blockIdx.z;
    const float* W = (bz == 0) ? wq : (bz == 1) ? wk : wv;
    float* C = (bz == 0) ? g_q : (bz == 1) ? g_k : g_v;

    __shared__ float As[2][BK][BM];
    __shared__ float Bs[2][BK][BN];

    int tid = threadIdx.x;
    int tr = (tid >> 4) * TM, tc = (tid & 15) * TN;
    int lrow = tid >> 2, lc4 = (tid & 3) * 4;

    const float* Ab = x + (size_t)(by * BM + lrow) * K + lc4;
    const float* Bt = W + (size_t)(bx * BN + lrow) * K + lc4;

    float4 pa0 = *(const float4*)(Ab);
    float4 pa1 = *(const float4*)(Ab + (size_t)64 * K);
    float4 pb0 = *(const float4*)(Bt);
    float4 pb1 = *(const float4*)(Bt + (size_t)64 * K);
    STORE_KT(As, 0, pa0, pa1)
    STORE_KT(Bs, 0, pb0, pb1)
    __syncthreads();

    float acc[TM][TN] = {};
    int buf = 0;
    const int niter = K / BK;
    for (int it = 0; it < niter; ++it) {
        if (it + 1 < niter) {
            int k0n = (it + 1) * BK;
            pa0 = *(const float4*)(Ab + k0n);
            pa1 = *(const float4*)(Ab + (size_t)64 * K + k0n);
            pb0 = *(const float4*)(Bt + k0n);
            pb1 = *(const float4*)(Bt + (size_t)64 * K + k0n);
        }
        COMPUTE_TILE(buf)
        if (it + 1 < niter) {
            int nb = buf ^ 1;
            STORE_KT(As, nb, pa0, pa1)
            STORE_KT(Bs, nb, pb0, pb1)
            __syncthreads();
            buf = nb;
        }
    }
    EPILOGUE(C, N)
}

// ---------------------------------------------------------------------------
// scores[b,s,t] = q.k  NT GEMM per batch (grid.z), causal tile skip.
__global__ void __launch_bounds__(256, 2) scores_nt()
{
    int bx = blockIdx.x, by = blockIdx.y, bz = blockIdx.z;
    if (bx > by) return;  // tile entirely above diagonal

    const int K = Dd, N = Ss;
    const float* A = g_q + (size_t)bz * Ss * Dd;
    const float* B = g_k + (size_t)bz * Ss * Dd;
    float*       C = g_p + (size_t)bz * Ss * Ss;

    __shared__ float As[2][BK][BM];
    __shared__ float Bs[2][BK][BN];

    int tid = threadIdx.x;
    int tr = (tid >> 4) * TM, tc = (tid & 15) * TN;
    int lrow = tid >> 2, lc4 = (tid & 3) * 4;

    const float* Ab = A + (size_t)(by * BM + lrow) * K + lc4;
    const float* Bt = B + (size_t)(bx * BN + lrow) * K + lc4;

    float4 pa0 = *(const float4*)(Ab);
    float4 pa1 = *(const float4*)(Ab + (size_t)64 * K);
    float4 pb0 = *(const float4*)(Bt);
    float4 pb1 = *(const float4*)(Bt + (size_t)64 * K);
    STORE_KT(As, 0, pa0, pa1)
    STORE_KT(Bs, 0, pb0, pb1)
    __syncthreads();

    float acc[TM][TN] = {};
    int buf = 0;
    const int niter = K / BK;
    for (int it = 0; it < niter; ++it) {
        if (it + 1 < niter) {
            int k0n = (it + 1) * BK;
            pa0 = *(const float4*)(Ab + k0n);
            pa1 = *(const float4*)(Ab + (size_t)64 * K + k0n);
            pb0 = *(const float4*)(Bt + k0n);
            pb1 = *(const float4*)(Bt + (size_t)64 * K + k0n);
        }
        COMPUTE_TILE(buf)
        if (it + 1 < niter) {
            int nb = buf ^ 1;
            STORE_KT(As, nb, pa0, pa1)
            STORE_KT(Bs, nb, pb0, pb1)
            __syncthreads();
            buf = nb;
        }
    }
    EPILOGUE(C, N)
}

// ---------------------------------------------------------------------------
// Row-wise causal softmax on full g_p (in place). Applies 1/sqrt(D) inside.
__global__ void __launch_bounds__(256) softmax_causal()
{
    const int S = Ss;
    int row = blockIdx.x;                // 0..B*S-1
    int b = row >> 11, s = row & (S - 1);
    float* p = g_p + (size_t)b * S * S + (size_t)s * S;
    int L = s + 1;
    const float scale = 0.03125f;        // 1/sqrt(1024)
    int tid = threadIdx.x;

    __shared__ float red[8];

    float m = -1e30f;
    for (int i = tid; i < L; i += 256) m = fmaxf(m, p[i]);
    #pragma unroll
    for (int o = 16; o; o >>= 1) m = fmaxf(m, __shfl_xor_sync(0xFFFFFFFFu, m, o));
    if ((tid & 31) == 0) red[tid >> 5] = m;
    __syncthreads();
    if (tid == 0) {
        float mm = red[0];
        #pragma unroll
        for (int i = 1; i < 8; i++) mm = fmaxf(mm, red[i]);
        red[0] = mm;
    }
    __syncthreads();
    m = red[0] * scale;
    __syncthreads();

    float sum = 0.f;
    for (int i = tid; i < L; i += 256) sum += __expf(p[i] * scale - m);
    #pragma unroll
    for (int o = 16; o; o >>= 1) sum += __shfl_xor_sync(0xFFFFFFFFu, sum, o);
    if ((tid & 31) == 0) red[tid >> 5] = sum;
    __syncthreads();
    if (tid == 0) {
        float ss = 0.f;
        #pragma unroll
        for (int i = 0; i < 8; i++) ss += red[i];
        red[0] = ss;
    }
    __syncthreads();
    float inv = 1.0f / red[0];

    for (int i = tid; i < S; i += 256)
        p[i] = (i < L) ? __expf(p[i] * scale - m) * inv : 0.0f;
}

// ---------------------------------------------------------------------------
// out[b,s,d] = P[b,s,:] @ V[b,:,d]  NN GEMM; k-loop stops at causal diagonal.
__global__ void __launch_bounds__(256, 2) av_nn(float* __restrict__ out)
{
    int bx = blockIdx.x, by = blockIdx.y, bz = blockIdx.z;
    const int K = Ss, N = Dd;
    const float* A  = g_p + (size_t)bz * Ss * Ss;
    const float* Bm = g_v + (size_t)bz * Ss * Dd;
    float*       C  = out + (size_t)bz * Ss * Dd;

    int kmax = (by + 1) * BM;
    if (kmax > K) kmax = K;

    __shared__ float As[2][BK][BM];
    __shared__ float Bs[2][BK][BN];

    int tid = threadIdx.x;
    int tr = (tid >> 4) * TM, tc = (tid & 15) * TN;
    int lrow = tid >> 2, lc4 = (tid & 3) * 4;
    int brow = tid >> 5, bcc = (tid & 31) * 4;   // B-tile mapping (N-major)

    const float* Ab = A + (size_t)(by * BM + lrow) * K + lc4;
    const float* Bb = Bm + bx * BN + bcc;

    float4 pa0 = *(const float4*)(Ab);
    float4 pa1 = *(const float4*)(Ab + (size_t)64 * K);
    float4 pb0 = *(const float4*)(Bb + (size_t)brow * N);
    float4 pb1 = *(const float4*)(Bb + (size_t)(brow + 8) * N);
    STORE_KT(As, 0, pa0, pa1)
    *(float4*)&Bs[0][brow][bcc]     = pb0;
    *(float4*)&Bs[0][brow + 8][bcc] = pb1;
    __syncthreads();

    float acc[TM][TN] = {};
    int buf = 0;
    const int niter = kmax / BK;
    for (int it = 0; it < niter; ++it) {
        if (it + 1 < niter) {
            int k0n = (it + 1) * BK;
            pa0 = *(const float4*)(Ab + k0n);
            pa1 = *(const float4*)(Ab + (size_t)64 * K + k0n);
            pb0 = *(const float4*)(Bb + (size_t)(k0n + brow) * N);
            pb1 = *(const float4*)(Bb + (size_t)(k0n + brow + 8) * N);
        }
        COMPUTE_TILE(buf)
        if (it + 1 < niter) {
            int nb = buf ^ 1;
            STORE_KT(As, nb, pa0, pa1)
            *(float4*)&Bs[nb][brow][bcc]     = pb0;
            *(float4*)&Bs[nb][brow + 8][bcc] = pb1;
            __syncthreads();
            buf = nb;
        }
    }
    EPILOGUE(C, N)
}

extern "C" void kernel_launch(void* const* d_in, const int* in_sizes, int n_in,
                              void* d_out, int out_size)
{
    const float* x  = (const float*)d_in[0];
    const float* wq = (const float*)d_in[1];
    const float* wk = (const float*)d_in[2];
    const float* wv = (const float*)d_in[3];
    float* out = (float*)d_out;

    dim3 blk(256);

    proj_all<<<dim3(Dd / BN, (Bb * Ss) / BM, 3), blk>>>(x, wq, wk, wv);
    scores_nt<<<dim3(Ss / BN, Ss / BM, Bb), blk>>>();
    softmax_causal<<<Bb * Ss, blk>>>();
    av_nn<<<dim3(Dd / BN, Ss / BM, Bb), blk>>>(out);
}